// round 1
// baseline (speedup 1.0000x reference)
#include <cuda_runtime.h>

namespace {

constexpr int N = 8;      // seq len
constexpr int D = 12;     // embed dim
constexpr int F = 24;     // ff dim
constexpr int V = 128;    // vocab
constexpr int WARPS = 8;  // warps (= items) per block
constexpr int THREADS = WARPS * 32;

__global__ __launch_bounds__(THREADS)
void tiny_transformer_kernel(
    const int*   __restrict__ x,
    const float* __restrict__ embed,
    const float* __restrict__ pos,
    const float* __restrict__ Wq, const float* __restrict__ bq,
    const float* __restrict__ Wk, const float* __restrict__ bk,
    const float* __restrict__ Wv, const float* __restrict__ bv,
    const float* __restrict__ Wo, const float* __restrict__ bo,
    const float* __restrict__ W1, const float* __restrict__ b1,
    const float* __restrict__ W2, const float* __restrict__ b2,
    const float* __restrict__ blm,
    float* __restrict__ out)
{
    // ---- block-shared weights ----
    __shared__ __align__(16) float sEmbT[D * V];   // transposed: [d][v]
    __shared__ float sPos[N * D];
    __shared__ float sWq[D * D], sWk[D * D], sWv[D * D], sWo[D * D];
    __shared__ float sBq[D], sBk[D], sBv[D], sBo[D];
    __shared__ float sW1[F * D], sB1[F];
    __shared__ float sW2[D * F], sB2[D];
    __shared__ __align__(16) float sBlm[V];

    // ---- per-warp scratch ----
    __shared__ float sX[WARPS][N * D];
    __shared__ float sQ[WARPS][N * D];
    __shared__ float sK[WARPS][N * D];
    __shared__ float sV[WARPS][N * D];
    __shared__ float sS[WARPS][N * N];
    __shared__ float sA[WARPS][N * D];
    __shared__ float sH[WARPS][N * F];
    __shared__ int   sTok[WARPS][N];

    const int tid = threadIdx.x;

    // cooperative weight staging
    for (int i = tid; i < D * V; i += THREADS) {
        int d = i / V, v = i % V;
        sEmbT[i] = embed[v * D + d];
    }
    for (int i = tid; i < N * D; i += THREADS) sPos[i] = pos[i];
    for (int i = tid; i < D * D; i += THREADS) {
        sWq[i] = Wq[i]; sWk[i] = Wk[i]; sWv[i] = Wv[i]; sWo[i] = Wo[i];
    }
    for (int i = tid; i < D; i += THREADS) {
        sBq[i] = bq[i]; sBk[i] = bk[i]; sBv[i] = bv[i]; sBo[i] = bo[i]; sB2[i] = b2[i];
    }
    for (int i = tid; i < F * D; i += THREADS) { sW1[i] = W1[i]; sW2[i] = W2[i]; }
    for (int i = tid; i < F; i += THREADS) sB1[i] = b1[i];
    for (int i = tid; i < V; i += THREADS) sBlm[i] = blm[i];
    __syncthreads();

    const int w    = tid >> 5;
    const int lane = tid & 31;
    const int item = blockIdx.x * WARPS + w;

    float* X  = sX[w];
    float* Q  = sQ[w];
    float* K  = sK[w];
    float* Vv = sV[w];
    float* S  = sS[w];
    float* A  = sA[w];
    float* H  = sH[w];

    if (lane < N) sTok[w][lane] = x[item * N + lane];
    __syncwarp();

    // phase 1: X = embed[x] + pos
    for (int i = lane; i < N * D; i += 32) {
        int n = i / D, d = i % D;
        X[i] = sEmbT[d * V + sTok[w][n]] + sPos[i];
    }
    __syncwarp();

    // phase 2: Q, K, V projections (96 outputs each, 12-FMA dot products)
    for (int i = lane; i < 3 * N * D; i += 32) {
        int which = i / (N * D);
        int r = i - which * (N * D);
        int n = r / D, d = r % D;
        const float* W  = (which == 0) ? sWq : (which == 1) ? sWk : sWv;
        const float* bb = (which == 0) ? sBq : (which == 1) ? sBk : sBv;
        float acc = bb[d];
        #pragma unroll
        for (int e = 0; e < D; e++) acc += X[n * D + e] * W[d * D + e];
        float* dst = (which == 0) ? Q : (which == 1) ? K : Vv;
        dst[r] = acc;
    }
    __syncwarp();

    // phase 3: scores S[n][m] = <Q_n, K_m> / sqrt(D)
    const float inv_scale = 0.28867513459481287f;  // 1/sqrt(12)
    for (int i = lane; i < N * N; i += 32) {
        int n = i / N, m = i % N;
        float acc = 0.f;
        #pragma unroll
        for (int e = 0; e < D; e++) acc += Q[n * D + e] * K[m * D + e];
        S[i] = acc * inv_scale;
    }
    __syncwarp();

    // phase 4: causal softmax (lane n owns row n); masked cols become weight 0
    if (lane < N) {
        const int n = lane;
        float mx = -3.4e38f;
        for (int m = 0; m <= n; m++) mx = fmaxf(mx, S[n * N + m]);
        float sum = 0.f;
        for (int m = 0; m <= n; m++) {
            float e = __expf(S[n * N + m] - mx);
            S[n * N + m] = e;
            sum += e;
        }
        float inv = 1.f / sum;
        for (int m = 0; m <= n; m++) S[n * N + m] *= inv;
        for (int m = n + 1; m < N; m++) S[n * N + m] = 0.f;
    }
    __syncwarp();

    // phase 5: A = softmax @ V  (zeros implement causality)
    for (int i = lane; i < N * D; i += 32) {
        int n = i / D, d = i % D;
        float acc = 0.f;
        #pragma unroll
        for (int m = 0; m < N; m++) acc += S[n * N + m] * Vv[m * D + d];
        A[i] = acc;
    }
    __syncwarp();

    // phase 6: X += A @ Wo^T + bo   (each lane touches only its own X[i])
    for (int i = lane; i < N * D; i += 32) {
        int n = i / D, d = i % D;
        float acc = sBo[d];
        #pragma unroll
        for (int e = 0; e < D; e++) acc += A[n * D + e] * sWo[d * D + e];
        X[i] += acc;
    }
    __syncwarp();

    // phase 7: H = relu(X @ W1^T + b1)
    for (int i = lane; i < N * F; i += 32) {
        int n = i / F, f = i % F;
        float acc = sB1[f];
        #pragma unroll
        for (int e = 0; e < D; e++) acc += X[n * D + e] * sW1[f * D + e];
        H[i] = fmaxf(acc, 0.f);
    }
    __syncwarp();

    // phase 8: X += H @ W2^T + b2
    for (int i = lane; i < N * D; i += 32) {
        int n = i / D, d = i % D;
        float acc = sB2[d];
        #pragma unroll
        for (int f = 0; f < F; f++) acc += H[n * F + f] * sW2[d * F + f];
        X[i] += acc;
    }
    __syncwarp();

    // phase 9: logits = X @ embed^T + b_lm  -> coalesced float4 stores
    const int v0 = lane * 4;
    float4 eT[D];
    #pragma unroll
    for (int d = 0; d < D; d++)
        eT[d] = *reinterpret_cast<const float4*>(&sEmbT[d * V + v0]);
    const float4 bl = *reinterpret_cast<const float4*>(&sBlm[v0]);

    float4* outp = reinterpret_cast<float4*>(out + (size_t)item * (N * V));
    #pragma unroll
    for (int n = 0; n < N; n++) {
        float4 acc = bl;
        #pragma unroll
        for (int d = 0; d < D; d++) {
            const float xv = X[n * D + d];
            acc.x += xv * eT[d].x;
            acc.y += xv * eT[d].y;
            acc.z += xv * eT[d].z;
            acc.w += xv * eT[d].w;
        }
        outp[n * (V / 4) + lane] = acc;
    }
}

}  // namespace

extern "C" void kernel_launch(void* const* d_in, const int* in_sizes, int n_in,
                              void* d_out, int out_size)
{
    const int*   x     = (const int*)  d_in[0];
    const float* embed = (const float*)d_in[1];
    const float* pos   = (const float*)d_in[2];
    const float* Wq    = (const float*)d_in[3];
    const float* bq    = (const float*)d_in[4];
    const float* Wk    = (const float*)d_in[5];
    const float* bk    = (const float*)d_in[6];
    const float* Wv    = (const float*)d_in[7];
    const float* bv    = (const float*)d_in[8];
    const float* Wo    = (const float*)d_in[9];
    const float* bo    = (const float*)d_in[10];
    const float* W1    = (const float*)d_in[11];
    const float* b1    = (const float*)d_in[12];
    const float* W2    = (const float*)d_in[13];
    const float* b2    = (const float*)d_in[14];
    const float* blm   = (const float*)d_in[15];
    float* out = (float*)d_out;

    const int batch = in_sizes[0] / N;           // 32768
    const int blocks = batch / WARPS;            // 4096

    tiny_transformer_kernel<<<blocks, THREADS>>>(
        x, embed, pos, Wq, bq, Wk, bk, Wv, bv, Wo, bo,
        W1, b1, W2, b2, blm, out);
}